// round 6
// baseline (speedup 1.0000x reference)
#include <cuda_runtime.h>
#include <cuda_bf16.h>
#include <cstdint>

// Problem constants
#define Cc 4
#define Bb 2
#define Dd 128
#define NTOK 65536          // F*T per batch
#define TOK 32              // tokens per CTA
#define NTILES 4096         // (Bb*NTOK)/TOK

typedef unsigned long long u64;

// ---------------- composed-weight scratch (device globals: no allocation) ----
__device__ float g_WqT[128 * 128];   // [k][o]  Wq_eff[o][k] = (in_w[0:128] @ Wq)[o][k]
__device__ float g_Wk [128 * 128];   // [r][k]  Wk_eff (row-major)
__device__ float g_WvT[128 * 128];   // [k][r]  Wv_eff transposed
__device__ float g_OwT[128 * 128];   // [o][d]  out_w transposed
__device__ float g_bq [128];         // composed q bias
__device__ float g_bv [128];         // composed v bias

// ---------------- f32x2 helpers ---------------------------------------------
__device__ __forceinline__ u64 ffma2(u64 a, u64 b, u64 c) {
    u64 d;
    asm("fma.rn.f32x2 %0, %1, %2, %3;" : "=l"(d) : "l"(a), "l"(b), "l"(c));
    return d;
}
__device__ __forceinline__ u64 pack2(float lo, float hi) {
    u64 r;
    asm("mov.b64 %0, {%1, %2};" : "=l"(r) : "f"(lo), "f"(hi));
    return r;
}
__device__ __forceinline__ float2 unpack2(u64 v) {
    float2 r;
    asm("mov.b64 {%0, %1}, %2;" : "=f"(r.x), "=f"(r.y) : "l"(v));
    return r;
}

// ---------------- prep: compose weights --------------------------------------
// Folds the module projections into MHA's packed in_proj:
//   Wq_eff = in_w[0:128]   @ Wq ; bq_eff = in_w[0:128]@bq + in_b[0:128]
//   Wk_eff = in_w[128:256] @ Wk ; (k bias is constant over softmax axis -> dropped)
//   Wv_eff = in_w[256:384] @ Wv ; bv_eff = in_w[256:384]@bv + in_b[256:384]
__global__ void prep_kernel(const float* __restrict__ Wq, const float* __restrict__ bq,
                            const float* __restrict__ Wk, const float* __restrict__ bk,
                            const float* __restrict__ Wv, const float* __restrict__ bv,
                            const float* __restrict__ in_w, const float* __restrict__ in_b,
                            const float* __restrict__ out_w, const float* __restrict__ out_b) {
    (void)bk; (void)out_b;
    const int blk = blockIdx.x;
    const int t = threadIdx.x;
    if (blk < 128) {
        const int o = blk;
        float acc = 0.f;
        #pragma unroll 8
        for (int m = 0; m < 128; m++) acc += in_w[o * 128 + m] * Wq[m * 128 + t];
        g_WqT[t * 128 + o] = acc;
        if (t == 0) {
            float s = in_b[o];
            for (int m = 0; m < 128; m++) s += in_w[o * 128 + m] * bq[m];
            g_bq[o] = s;
        }
    } else if (blk < 256) {
        const int r = blk - 128;
        float acc = 0.f;
        #pragma unroll 8
        for (int m = 0; m < 128; m++) acc += in_w[(128 + r) * 128 + m] * Wk[m * 128 + t];
        g_Wk[r * 128 + t] = acc;
    } else if (blk < 384) {
        const int r = blk - 256;
        float acc = 0.f;
        #pragma unroll 8
        for (int m = 0; m < 128; m++) acc += in_w[(256 + r) * 128 + m] * Wv[m * 128 + t];
        g_WvT[t * 128 + r] = acc;
        if (t == 0) {
            float s = in_b[256 + r];
            for (int m = 0; m < 128; m++) s += in_w[(256 + r) * 128 + m] * bv[m];
            g_bv[r] = s;
        }
    } else {
        const int d = blk - 384;
        g_OwT[t * 128 + d] = out_w[d * 128 + t];  // OwT[o][d]
    }
}

// ---------------- fused main kernel ------------------------------------------
// smem float layout (45824 floats = 183296 B):
//  [0      .. 4096)  raw c0 tile [d][t]            (residual)
//  [4096   .. 20480) normalized kv  [c][d][t]
//  [20480  .. 24576) normalized q   [d][t]   -> reused as output stage
//  [24576  .. 28672) qfull [o][t]            -> reused as ctx [o][t]
//  [28672  .. 45056) qk [h][j][t]            -> reused as mix [h][j][t]
//  [45056  .. 45568) scores/attn [t][h][c]
//  [45568  .. 45696) mean [c][t]
//  [45696  .. 45824) rstd [c][t]
__global__ void __launch_bounds__(512, 1)
cca_main(const float* __restrict__ h_all,
         const float* __restrict__ ln_q_g, const float* __restrict__ ln_q_b,
         const float* __restrict__ ln_kv_g, const float* __restrict__ ln_kv_b,
         const float* __restrict__ out_b,
         float* __restrict__ out) {
    extern __shared__ float sm[];
    float* s_raw0 = sm;
    float* s_x    = sm + 4096;
    float* s_xq   = sm + 20480;
    float* s_qf   = sm + 24576;
    float* s_qk   = sm + 28672;
    float* s_sc   = sm + 45056;
    float* s_mean = sm + 45568;
    float* s_rstd = sm + 45696;

    const int tid  = threadIdx.x;
    const int w    = tid >> 5;
    const int lane = tid & 31;
    const int tile = blockIdx.x;
    const int b    = tile >> 11;            // 2048 tiles per batch element
    const int tok0 = (tile & 2047) * TOK;

    // ---- P1: load tile (coalesced 128B rows), raw into smem -----------------
    {
        const int t = lane;
        #pragma unroll
        for (int c = 0; c < 4; c++) {
            const float* src = h_all + (size_t)(c * Bb + b) * Dd * NTOK + tok0 + t;
            #pragma unroll
            for (int pass = 0; pass < 8; pass++) {
                const int d = pass * 16 + w;
                float v = __ldg(src + (size_t)d * NTOK);
                s_x[c * 4096 + d * 32 + t] = v;
                if (c == 0) s_raw0[d * 32 + t] = v;
            }
        }
    }
    __syncthreads();

    // ---- LN stats (biased variance, eps 1e-5) -------------------------------
    if (tid < 128) {
        const int c = tid >> 5, t = tid & 31;
        float s = 0.f, ss = 0.f;
        const float* p = &s_x[c * 4096 + t];
        #pragma unroll 8
        for (int d = 0; d < 128; d++) { float v = p[d * 32]; s += v; ss += v * v; }
        const float mean = s * (1.f / 128.f);
        const float var  = ss * (1.f / 128.f) - mean * mean;
        s_mean[c * 32 + t] = mean;
        s_rstd[c * 32 + t] = rsqrtf(var + 1e-5f);
    }
    __syncthreads();

    // ---- normalize: kv-affine in place, q-affine into s_xq ------------------
    {
        const int t = lane;
        #pragma unroll
        for (int pass = 0; pass < 8; pass++) {
            const int d = pass * 16 + w;
            const float gkv = __ldg(ln_kv_g + d), bkv = __ldg(ln_kv_b + d);
            const float gq  = __ldg(ln_q_g + d),  bq_ = __ldg(ln_q_b + d);
            #pragma unroll
            for (int c = 0; c < 4; c++) {
                const float v   = s_x[c * 4096 + d * 32 + t];
                const float nrm = (v - s_mean[c * 32 + t]) * s_rstd[c * 32 + t];
                s_x[c * 4096 + d * 32 + t] = nrm * gkv + bkv;
                if (c == 0) s_xq[d * 32 + t] = nrm * gq + bq_;
            }
        }
    }
    __syncthreads();

    const int og = w & 3;          // output-dim group (or head)
    const int t0 = (w >> 2) * 8;   // 8 tokens per warp

    // ---- P2: qfull[o][t] = LNq @ Wq_eff^T + bq_eff  (f32x2) -----------------
    {
        const int o = og * 32 + lane;
        const float bqv = g_bq[o];
        u64 a0 = pack2(bqv, bqv), a1 = a0, a2 = a0, a3 = a0;
        const float* wp = g_WqT + o;      // stride 128 over k
        const float* xp = s_xq + t0;
        #pragma unroll 4
        for (int kk = 0; kk < 128; kk++) {
            const float wv = wp[kk * 128];
            const u64 ww = pack2(wv, wv);
            const u64* x = (const u64*)(xp + kk * 32);   // uniform addr -> broadcast
            a0 = ffma2(ww, x[0], a0);
            a1 = ffma2(ww, x[1], a1);
            a2 = ffma2(ww, x[2], a2);
            a3 = ffma2(ww, x[3], a3);
        }
        u64* dst = (u64*)(s_qf + o * 32 + t0);
        dst[0] = a0; dst[1] = a1; dst[2] = a2; dst[3] = a3;
    }
    __syncthreads();

    // ---- P3: qk[h][j][t] = sum_i qfull[t][h*32+i] * Wk_eff[h*32+i][j] -------
    {
        const int h = og;
        u64 acc[4][4];
        #pragma unroll
        for (int m = 0; m < 4; m++)
            #pragma unroll
            for (int p = 0; p < 4; p++) acc[m][p] = 0ull;
        #pragma unroll 2
        for (int i = 0; i < 32; i++) {
            const int row = h * 32 + i;
            const float* wr = g_Wk + row * 128 + lane;
            const u64* x = (const u64*)(s_qf + row * 32 + t0);
            const u64 x0 = x[0], x1 = x[1], x2 = x[2], x3 = x[3];
            #pragma unroll
            for (int m = 0; m < 4; m++) {
                const float wv = wr[m * 32];
                const u64 ww = pack2(wv, wv);
                acc[m][0] = ffma2(ww, x0, acc[m][0]);
                acc[m][1] = ffma2(ww, x1, acc[m][1]);
                acc[m][2] = ffma2(ww, x2, acc[m][2]);
                acc[m][3] = ffma2(ww, x3, acc[m][3]);
            }
        }
        #pragma unroll
        for (int m = 0; m < 4; m++) {
            const int j = lane + 32 * m;
            u64* dst = (u64*)(s_qk + h * 4096 + j * 32 + t0);
            dst[0] = acc[m][0]; dst[1] = acc[m][1];
            dst[2] = acc[m][2]; dst[3] = acc[m][3];
        }
    }
    __syncthreads();

    // ---- P4: scores + softmax over c (k-bias provably cancels) --------------
    {
        const int t = tid & 31, idx = tid >> 5;
        const int h = idx & 3, c = idx >> 2;
        const float* qp = s_qk + h * 4096 + t;
        const float* xp = s_x + c * 4096 + t;
        float s = 0.f;
        #pragma unroll 8
        for (int j = 0; j < 128; j++) s += qp[j * 32] * xp[j * 32];
        s_sc[t * 16 + h * 4 + c] = s * 0.17677669529663687f;   // 1/sqrt(32)
    }
    __syncthreads();
    {
        const int t = tid & 31, idx = tid >> 5;
        const int h = idx & 3, c = idx >> 2;
        const float v0 = s_sc[t * 16 + h * 4 + 0];
        const float v1 = s_sc[t * 16 + h * 4 + 1];
        const float v2 = s_sc[t * 16 + h * 4 + 2];
        const float v3 = s_sc[t * 16 + h * 4 + 3];
        const float m  = fmaxf(fmaxf(v0, v1), fmaxf(v2, v3));
        const float e0 = __expf(v0 - m), e1 = __expf(v1 - m);
        const float e2 = __expf(v2 - m), e3 = __expf(v3 - m);
        const float inv = 1.f / (e0 + e1 + e2 + e3);
        const float mine = (c == 0 ? e0 : c == 1 ? e1 : c == 2 ? e2 : e3) * inv;
        __syncthreads();
        s_sc[t * 16 + h * 4 + c] = mine;
    }
    __syncthreads();

    // ---- P5: mix[h][j][t] = sum_c attn[t][h][c] * xkv[c][j][t]  (into s_qk) -
    {
        const int t = tid & 31, g = tid >> 5;
        #pragma unroll 4
        for (int q = 0; q < 32; q++) {
            const int p = q * 16 + g;
            const int h = p >> 7, j = p & 127;
            const float a0 = s_sc[t * 16 + h * 4 + 0];
            const float a1 = s_sc[t * 16 + h * 4 + 1];
            const float a2 = s_sc[t * 16 + h * 4 + 2];
            const float a3 = s_sc[t * 16 + h * 4 + 3];
            float mv = a0 * s_x[j * 32 + t]
                     + a1 * s_x[4096  + j * 32 + t]
                     + a2 * s_x[8192  + j * 32 + t]
                     + a3 * s_x[12288 + j * 32 + t];
            s_qk[h * 4096 + j * 32 + t] = mv;
        }
    }
    __syncthreads();

    // ---- P6: ctx[o][t] = mix[h=o/32] @ Wv_eff[o,:]^T + bv_eff  (into s_qf) --
    {
        const int o = og * 32 + lane;       // head = og
        const float bvv = g_bv[o];
        u64 a0 = pack2(bvv, bvv), a1 = a0, a2 = a0, a3 = a0;
        const float* wp = g_WvT + o;
        const float* xp = s_qk + og * 4096 + t0;
        #pragma unroll 4
        for (int j = 0; j < 128; j++) {
            const float wv = wp[j * 128];
            const u64 ww = pack2(wv, wv);
            const u64* x = (const u64*)(xp + j * 32);
            a0 = ffma2(ww, x[0], a0);
            a1 = ffma2(ww, x[1], a1);
            a2 = ffma2(ww, x[2], a2);
            a3 = ffma2(ww, x[3], a3);
        }
        u64* dst = (u64*)(s_qf + o * 32 + t0);
        dst[0] = a0; dst[1] = a1; dst[2] = a2; dst[3] = a3;
    }
    __syncthreads();

    // ---- P7: out[d][t] = ctx @ out_w^T + out_b + raw0  (stage into s_xq) ----
    {
        const int d = og * 32 + lane;
        const float ob = __ldg(out_b + d);
        u64 a0 = pack2(ob, ob), a1 = a0, a2 = a0, a3 = a0;
        const float* wp = g_OwT + d;
        const float* xp = s_qf + t0;
        #pragma unroll 4
        for (int o = 0; o < 128; o++) {
            const float wv = wp[o * 128];
            const u64 ww = pack2(wv, wv);
            const u64* x = (const u64*)(xp + o * 32);
            a0 = ffma2(ww, x[0], a0);
            a1 = ffma2(ww, x[1], a1);
            a2 = ffma2(ww, x[2], a2);
            a3 = ffma2(ww, x[3], a3);
        }
        const float2 f0 = unpack2(a0), f1 = unpack2(a1);
        const float2 f2 = unpack2(a2), f3 = unpack2(a3);
        float* dst = s_xq + d * 32 + t0;
        const float* rp = s_raw0 + d * 32 + t0;
        dst[0] = f0.x + rp[0]; dst[1] = f0.y + rp[1];
        dst[2] = f1.x + rp[2]; dst[3] = f1.y + rp[3];
        dst[4] = f2.x + rp[4]; dst[5] = f2.y + rp[5];
        dst[6] = f3.x + rp[6]; dst[7] = f3.y + rp[7];
    }
    __syncthreads();

    // ---- coalesced writeout (B, D, F*T) -------------------------------------
    {
        const int t = lane;
        float* dstg = out + (size_t)b * Dd * NTOK + tok0 + t;
        #pragma unroll
        for (int pass = 0; pass < 8; pass++) {
            const int d = pass * 16 + w;
            dstg[(size_t)d * NTOK] = s_xq[d * 32 + t];
        }
    }
}

// ---------------- launch ------------------------------------------------------
extern "C" void kernel_launch(void* const* d_in, const int* in_sizes, int n_in,
                              void* d_out, int out_size) {
    (void)in_sizes; (void)n_in; (void)out_size;
    const float* h_all   = (const float*)d_in[0];
    const float* ln_q_g  = (const float*)d_in[1];
    const float* ln_q_b  = (const float*)d_in[2];
    const float* ln_kv_g = (const float*)d_in[3];
    const float* ln_kv_b = (const float*)d_in[4];
    const float* Wq      = (const float*)d_in[5];
    const float* bq      = (const float*)d_in[6];
    const float* Wk      = (const float*)d_in[7];
    const float* bk      = (const float*)d_in[8];
    const float* Wv      = (const float*)d_in[9];
    const float* bv      = (const float*)d_in[10];
    const float* in_w    = (const float*)d_in[11];
    const float* in_b    = (const float*)d_in[12];
    const float* out_w   = (const float*)d_in[13];
    const float* out_b   = (const float*)d_in[14];
    float* out = (float*)d_out;

    prep_kernel<<<512, 128>>>(Wq, bq, Wk, bk, Wv, bv, in_w, in_b, out_w, out_b);

    const int smem_bytes = 45824 * sizeof(float);   // 183296 B
    cudaFuncSetAttribute(cca_main, cudaFuncAttributeMaxDynamicSharedMemorySize, smem_bytes);
    cca_main<<<NTILES, 512, smem_bytes>>>(h_all, ln_q_g, ln_q_b, ln_kv_g, ln_kv_b,
                                          out_b, out);
}

// round 8
// speedup vs baseline: 1.5166x; 1.5166x over previous
#include <cuda_runtime.h>
#include <cuda_bf16.h>
#include <cstdint>

// Problem constants
#define Cc 4
#define Bb 2
#define Dd 128
#define NTOK 65536          // F*T per batch
#define TOK 32              // tokens per CTA
#define NTILES 4096         // (Bb*NTOK)/TOK

typedef unsigned long long u64;

// ---------------- composed-weight scratch (device globals: no allocation) ----
__device__ float g_WqT[128 * 128];   // [k][o]  Wq_eff[o][k] = (in_w[0:128] @ Wq)[o][k]
__device__ float g_Wk [128 * 128];   // [r][k]  Wk_eff (row-major)
__device__ float g_WvT[128 * 128];   // [k][r]  Wv_eff transposed
__device__ float g_OwT[128 * 128];   // [o][d]  out_w transposed
__device__ float g_bq [128];         // composed q bias
__device__ float g_bv [128];         // composed v bias

// ---------------- f32x2 / bf16 helpers --------------------------------------
__device__ __forceinline__ u64 ffma2(u64 a, u64 b, u64 c) {
    u64 d;
    asm("fma.rn.f32x2 %0, %1, %2, %3;" : "=l"(d) : "l"(a), "l"(b), "l"(c));
    return d;
}
__device__ __forceinline__ u64 pack2(float lo, float hi) {
    u64 r;
    asm("mov.b64 %0, {%1, %2};" : "=l"(r) : "f"(lo), "f"(hi));
    return r;
}
__device__ __forceinline__ float2 unpack2(u64 v) {
    float2 r;
    asm("mov.b64 {%0, %1}, %2;" : "=f"(r.x), "=f"(r.y) : "l"(v));
    return r;
}
// cvt d, A, B -> d.lo = B, d.hi = A  (per ptx_helpers convention)
__device__ __forceinline__ unsigned pack_bf16x2(float lo, float hi) {
    unsigned r;
    asm("cvt.rn.bf16x2.f32 %0, %1, %2;" : "=r"(r) : "f"(hi), "f"(lo));
    return r;
}
__device__ __forceinline__ unsigned short f2bf(float f) {
    unsigned short h;
    asm("cvt.rn.bf16.f32 %0, %1;" : "=h"(h) : "f"(f));
    return h;
}
__device__ __forceinline__ float bf2f(unsigned short h) {
    return __uint_as_float(((unsigned)h) << 16);
}

// ---------------- prep: compose weights --------------------------------------
__global__ void prep_kernel(const float* __restrict__ Wq, const float* __restrict__ bq,
                            const float* __restrict__ Wk, const float* __restrict__ bk,
                            const float* __restrict__ Wv, const float* __restrict__ bv,
                            const float* __restrict__ in_w, const float* __restrict__ in_b,
                            const float* __restrict__ out_w, const float* __restrict__ out_b) {
    (void)bk; (void)out_b;
    const int blk = blockIdx.x;
    const int t = threadIdx.x;
    if (blk < 128) {
        const int o = blk;
        float acc = 0.f;
        #pragma unroll 8
        for (int m = 0; m < 128; m++) acc += in_w[o * 128 + m] * Wq[m * 128 + t];
        g_WqT[t * 128 + o] = acc;
        if (t == 0) {
            float s = in_b[o];
            for (int m = 0; m < 128; m++) s += in_w[o * 128 + m] * bq[m];
            g_bq[o] = s;
        }
    } else if (blk < 256) {
        const int r = blk - 128;
        float acc = 0.f;
        #pragma unroll 8
        for (int m = 0; m < 128; m++) acc += in_w[(128 + r) * 128 + m] * Wk[m * 128 + t];
        g_Wk[r * 128 + t] = acc;
    } else if (blk < 384) {
        const int r = blk - 256;
        float acc = 0.f;
        #pragma unroll 8
        for (int m = 0; m < 128; m++) acc += in_w[(256 + r) * 128 + m] * Wv[m * 128 + t];
        g_WvT[t * 128 + r] = acc;
        if (t == 0) {
            float s = in_b[256 + r];
            for (int m = 0; m < 128; m++) s += in_w[(256 + r) * 128 + m] * bv[m];
            g_bv[r] = s;
        }
    } else {
        const int d = blk - 384;
        g_OwT[t * 128 + d] = out_w[d * 128 + t];  // OwT[o][d]
    }
}

// ---------------- fused main kernel ------------------------------------------
// smem layout (25344 floats = 101376 B -> 2 CTAs/SM):
//  [0      .. 4096)   s_xq   fp32  q-normalized [d][t]  -> reused as staged out
//  [4096   .. 8192)   s_qf   fp32  qfull/ctx [o][t]     (aliased: LN partials)
//  [8192   .. 16384)  s_x16  bf16  normalized kv [c][d][t]  (16384 elems)
//  [16384  .. 24576)  s_qk16 bf16  qk / mix [h][j][t]       (16384 elems)
//  [24576  .. 25088)  s_sc   scores/attn [t][h][c]
//  [25088  .. 25216)  s_mean [c][t]
//  [25216  .. 25344)  s_rstd [c][t]
__global__ void __launch_bounds__(512, 2)
cca_main(const float* __restrict__ h_all,
         const float* __restrict__ ln_q_g, const float* __restrict__ ln_q_b,
         const float* __restrict__ ln_kv_g, const float* __restrict__ ln_kv_b,
         const float* __restrict__ out_b,
         float* __restrict__ out) {
    extern __shared__ float sm[];
    float* s_xq  = sm;
    float* s_qf  = sm + 4096;
    float* s_ps  = sm + 4096;                 // alias (dead before P2 writes s_qf)
    float* s_pss = sm + 6144;
    unsigned short* s_x16  = (unsigned short*)(sm + 8192);
    unsigned short* s_qk16 = (unsigned short*)(sm + 16384);
    float* s_sc   = sm + 24576;
    float* s_mean = sm + 25088;
    float* s_rstd = sm + 25216;

    const int tid  = threadIdx.x;
    const int w    = tid >> 5;
    const int lane = tid & 31;
    const int tile = blockIdx.x;
    const int b    = tile >> 11;            // 2048 tiles per batch element
    const int tok0 = (tile & 2047) * TOK;

    // ---- P1a: streaming partial LN stats (no raw staging) -------------------
    {
        #pragma unroll
        for (int c = 0; c < 4; c++) {
            const float* src = h_all + (size_t)(c * Bb + b) * Dd * NTOK + tok0 + lane;
            float s = 0.f, ss = 0.f;
            #pragma unroll
            for (int pass = 0; pass < 8; pass++) {
                const int d = pass * 16 + w;
                const float v = __ldg(src + (size_t)d * NTOK);
                s += v; ss += v * v;
            }
            s_ps [(c * 16 + w) * 32 + lane] = s;
            s_pss[(c * 16 + w) * 32 + lane] = ss;
        }
    }
    __syncthreads();

    // ---- P1b: finalize stats (biased variance, eps 1e-5) --------------------
    if (tid < 128) {
        const int c = tid >> 5, t = tid & 31;
        float s = 0.f, ss = 0.f;
        #pragma unroll
        for (int i = 0; i < 16; i++) {
            s  += s_ps [(c * 16 + i) * 32 + t];
            ss += s_pss[(c * 16 + i) * 32 + t];
        }
        const float mean = s * (1.f / 128.f);
        const float var  = ss * (1.f / 128.f) - mean * mean;
        s_mean[c * 32 + t] = mean;
        s_rstd[c * 32 + t] = rsqrtf(var + 1e-5f);
    }
    __syncthreads();

    // ---- P1c: reload (L2-hot) + normalize; kv -> bf16, q -> fp32 ------------
    {
        #pragma unroll
        for (int pass = 0; pass < 8; pass++) {
            const int d = pass * 16 + w;
            const float gkv = __ldg(ln_kv_g + d), bkv = __ldg(ln_kv_b + d);
            const float gq  = __ldg(ln_q_g + d),  bq_ = __ldg(ln_q_b + d);
            #pragma unroll
            for (int c = 0; c < 4; c++) {
                const float* src = h_all + (size_t)(c * Bb + b) * Dd * NTOK + tok0 + lane;
                const float v   = __ldg(src + (size_t)d * NTOK);
                const float nrm = (v - s_mean[c * 32 + lane]) * s_rstd[c * 32 + lane];
                s_x16[c * 4096 + d * 32 + lane] = f2bf(nrm * gkv + bkv);
                if (c == 0) s_xq[d * 32 + lane] = nrm * gq + bq_;
            }
        }
    }
    __syncthreads();

    const int og = w & 3;          // output-dim group (or head)
    const int t0 = (w >> 2) * 8;   // 8 tokens per warp

    // ---- P2: qfull[o][t] = LNq @ Wq_eff^T + bq_eff  (f32x2, LDS.128) --------
    {
        const int o = og * 32 + lane;
        const float bqv = g_bq[o];
        u64 a0 = pack2(bqv, bqv), a1 = a0, a2 = a0, a3 = a0;
        const float* wp = g_WqT + o;      // stride 128 over k
        const float* xp = s_xq + t0;
        #pragma unroll 4
        for (int kk = 0; kk < 128; kk++) {
            const float wv = wp[kk * 128];
            const u64 ww = pack2(wv, wv);
            const ulonglong2 xa = *(const ulonglong2*)(xp + kk * 32);
            const ulonglong2 xb = *(const ulonglong2*)(xp + kk * 32 + 4);
            a0 = ffma2(ww, xa.x, a0);
            a1 = ffma2(ww, xa.y, a1);
            a2 = ffma2(ww, xb.x, a2);
            a3 = ffma2(ww, xb.y, a3);
        }
        ulonglong2 o0; o0.x = a0; o0.y = a1;
        ulonglong2 o1; o1.x = a2; o1.y = a3;
        *(ulonglong2*)(s_qf + o * 32 + t0)     = o0;
        *(ulonglong2*)(s_qf + o * 32 + t0 + 4) = o1;
    }
    __syncthreads();

    // ---- P3: qk[h][j][t] = sum_i qfull[h*32+i][t] * Wk_eff[h*32+i][j] -------
    {
        const int h = og;
        u64 acc[4][4];
        #pragma unroll
        for (int m = 0; m < 4; m++)
            #pragma unroll
            for (int p = 0; p < 4; p++) acc[m][p] = 0ull;
        #pragma unroll 2
        for (int i = 0; i < 32; i++) {
            const int row = h * 32 + i;
            const float* wr = g_Wk + row * 128 + lane;
            const ulonglong2 xa = *(const ulonglong2*)(s_qf + row * 32 + t0);
            const ulonglong2 xb = *(const ulonglong2*)(s_qf + row * 32 + t0 + 4);
            #pragma unroll
            for (int m = 0; m < 4; m++) {
                const float wv = wr[m * 32];
                const u64 ww = pack2(wv, wv);
                acc[m][0] = ffma2(ww, xa.x, acc[m][0]);
                acc[m][1] = ffma2(ww, xa.y, acc[m][1]);
                acc[m][2] = ffma2(ww, xb.x, acc[m][2]);
                acc[m][3] = ffma2(ww, xb.y, acc[m][3]);
            }
        }
        #pragma unroll
        for (int m = 0; m < 4; m++) {
            const int j = lane + 32 * m;
            const float2 f0 = unpack2(acc[m][0]), f1 = unpack2(acc[m][1]);
            const float2 f2 = unpack2(acc[m][2]), f3 = unpack2(acc[m][3]);
            uint4 o4;
            o4.x = pack_bf16x2(f0.x, f0.y);
            o4.y = pack_bf16x2(f1.x, f1.y);
            o4.z = pack_bf16x2(f2.x, f2.y);
            o4.w = pack_bf16x2(f3.x, f3.y);
            *(uint4*)(s_qk16 + h * 4096 + j * 32 + t0) = o4;
        }
    }
    __syncthreads();

    // ---- P4: scores + softmax over c (k-bias provably cancels) --------------
    {
        const int t = tid & 31, idx = tid >> 5;
        const int h = idx & 3, c = idx >> 2;
        const unsigned short* qp = s_qk16 + h * 4096 + t;
        const unsigned short* xp = s_x16  + c * 4096 + t;
        float s = 0.f;
        #pragma unroll 8
        for (int j = 0; j < 128; j++) s += bf2f(qp[j * 32]) * bf2f(xp[j * 32]);
        s_sc[t * 16 + h * 4 + c] = s * 0.17677669529663687f;   // 1/sqrt(32)
    }
    __syncthreads();
    {
        const int t = tid & 31, idx = tid >> 5;
        const int h = idx & 3, c = idx >> 2;
        const float v0 = s_sc[t * 16 + h * 4 + 0];
        const float v1 = s_sc[t * 16 + h * 4 + 1];
        const float v2 = s_sc[t * 16 + h * 4 + 2];
        const float v3 = s_sc[t * 16 + h * 4 + 3];
        const float m  = fmaxf(fmaxf(v0, v1), fmaxf(v2, v3));
        const float e0 = __expf(v0 - m), e1 = __expf(v1 - m);
        const float e2 = __expf(v2 - m), e3 = __expf(v3 - m);
        const float inv = 1.f / (e0 + e1 + e2 + e3);
        const float mine = (c == 0 ? e0 : c == 1 ? e1 : c == 2 ? e2 : e3) * inv;
        __syncthreads();
        s_sc[t * 16 + h * 4 + c] = mine;
    }
    __syncthreads();

    // ---- P5: mix[h][j][t] = sum_c attn[t][h][c] * xkv[c][j][t]  (bf16 out) --
    {
        const int t = tid & 31, g = tid >> 5;
        #pragma unroll
        for (int h = 0; h < 4; h++) {
            const float a0 = s_sc[t * 16 + h * 4 + 0];
            const float a1 = s_sc[t * 16 + h * 4 + 1];
            const float a2 = s_sc[t * 16 + h * 4 + 2];
            const float a3 = s_sc[t * 16 + h * 4 + 3];
            #pragma unroll
            for (int jj = 0; jj < 8; jj++) {
                const int j = jj * 16 + g;
                const float mv = a0 * bf2f(s_x16[j * 32 + t])
                               + a1 * bf2f(s_x16[4096  + j * 32 + t])
                               + a2 * bf2f(s_x16[8192  + j * 32 + t])
                               + a3 * bf2f(s_x16[12288 + j * 32 + t]);
                s_qk16[h * 4096 + j * 32 + t] = f2bf(mv);
            }
        }
    }
    __syncthreads();

    // ---- P6: ctx[o][t] = mix[h=o/32] @ Wv_eff[o,:]^T + bv_eff (bf16 in) -----
    {
        const int o = og * 32 + lane;       // head = og
        const float bvv = g_bv[o];
        u64 a0 = pack2(bvv, bvv), a1 = a0, a2 = a0, a3 = a0;
        const float* wp = g_WvT + o;
        const unsigned short* xp = s_qk16 + og * 4096 + t0;
        #pragma unroll 4
        for (int j = 0; j < 128; j++) {
            const float wv = wp[j * 128];
            const u64 ww = pack2(wv, wv);
            const uint4 xv = *(const uint4*)(xp + j * 32);
            const u64 x0 = pack2(__uint_as_float(xv.x << 16), __uint_as_float(xv.x & 0xFFFF0000u));
            const u64 x1 = pack2(__uint_as_float(xv.y << 16), __uint_as_float(xv.y & 0xFFFF0000u));
            const u64 x2 = pack2(__uint_as_float(xv.z << 16), __uint_as_float(xv.z & 0xFFFF0000u));
            const u64 x3 = pack2(__uint_as_float(xv.w << 16), __uint_as_float(xv.w & 0xFFFF0000u));
            a0 = ffma2(ww, x0, a0);
            a1 = ffma2(ww, x1, a1);
            a2 = ffma2(ww, x2, a2);
            a3 = ffma2(ww, x3, a3);
        }
        ulonglong2 o0; o0.x = a0; o0.y = a1;
        ulonglong2 o1; o1.x = a2; o1.y = a3;
        *(ulonglong2*)(s_qf + o * 32 + t0)     = o0;   // overwrites qfull (done)
        *(ulonglong2*)(s_qf + o * 32 + t0 + 4) = o1;
    }
    __syncthreads();

    // ---- P7: staged[d][t] = ctx @ out_w^T + out_b  (residual added at store) -
    {
        const int d = og * 32 + lane;
        const float ob = __ldg(out_b + d);
        u64 a0 = pack2(ob, ob), a1 = a0, a2 = a0, a3 = a0;
        const float* wp = g_OwT + d;
        const float* xp = s_qf + t0;
        #pragma unroll 4
        for (int o = 0; o < 128; o++) {
            const float wv = wp[o * 128];
            const u64 ww = pack2(wv, wv);
            const ulonglong2 xa = *(const ulonglong2*)(xp + o * 32);
            const ulonglong2 xb = *(const ulonglong2*)(xp + o * 32 + 4);
            a0 = ffma2(ww, xa.x, a0);
            a1 = ffma2(ww, xa.y, a1);
            a2 = ffma2(ww, xb.x, a2);
            a3 = ffma2(ww, xb.y, a3);
        }
        ulonglong2 o0; o0.x = a0; o0.y = a1;
        ulonglong2 o1; o1.x = a2; o1.y = a3;
        *(ulonglong2*)(s_xq + d * 32 + t0)     = o0;   // overwrites xq (done)
        *(ulonglong2*)(s_xq + d * 32 + t0 + 4) = o1;
    }
    __syncthreads();

    // ---- writeout: add residual (re-read c0 raw, L2-likely) + coalesced STG -
    {
        const float* rsrc = h_all + (size_t)b * Dd * NTOK + tok0 + lane;   // c=0
        float* dstg = out + (size_t)b * Dd * NTOK + tok0 + lane;
        #pragma unroll
        for (int pass = 0; pass < 8; pass++) {
            const int d = pass * 16 + w;
            dstg[(size_t)d * NTOK] = s_xq[d * 32 + lane]
                                   + __ldg(rsrc + (size_t)d * NTOK);
        }
    }
}

// ---------------- launch ------------------------------------------------------
extern "C" void kernel_launch(void* const* d_in, const int* in_sizes, int n_in,
                              void* d_out, int out_size) {
    (void)in_sizes; (void)n_in; (void)out_size;
    const float* h_all   = (const float*)d_in[0];
    const float* ln_q_g  = (const float*)d_in[1];
    const float* ln_q_b  = (const float*)d_in[2];
    const float* ln_kv_g = (const float*)d_in[3];
    const float* ln_kv_b = (const float*)d_in[4];
    const float* Wq      = (const float*)d_in[5];
    const float* bq      = (const float*)d_in[6];
    const float* Wk      = (const float*)d_in[7];
    const float* bk      = (const float*)d_in[8];
    const float* Wv      = (const float*)d_in[9];
    const float* bv      = (const float*)d_in[10];
    const float* in_w    = (const float*)d_in[11];
    const float* in_b    = (const float*)d_in[12];
    const float* out_w   = (const float*)d_in[13];
    const float* out_b   = (const float*)d_in[14];
    float* out = (float*)d_out;

    prep_kernel<<<512, 128>>>(Wq, bq, Wk, bk, Wv, bv, in_w, in_b, out_w, out_b);

    const int smem_bytes = 25344 * sizeof(float);   // 101376 B -> 2 CTAs/SM
    cudaFuncSetAttribute(cca_main, cudaFuncAttributeMaxDynamicSharedMemorySize, smem_bytes);
    cca_main<<<NTILES, 512, smem_bytes>>>(h_all, ln_q_g, ln_q_b, ln_kv_g, ln_kv_b,
                                          out_b, out);
}